// round 1
// baseline (speedup 1.0000x reference)
#include <cuda_runtime.h>
#include <math.h>
#include <stdint.h>

// Problem constants
#define BB    2
#define SS    4096
#define DD    512
#define HH    8
#define DKK   64
#define DFFF  2048
#define MTOT  (BB*SS)          // 8192 rows

// ---------------------------------------------------------------------------
// Scratch (static device buffers; allocation-free per harness rules)
// ---------------------------------------------------------------------------
__device__ float g_q [(size_t)BB*HH*SS*DKK];   // (b,h,s,dk)
__device__ float g_k [(size_t)BB*HH*SS*DKK];
__device__ float g_v [(size_t)BB*HH*SS*DKK];
__device__ float g_o [(size_t)MTOT*DD];        // attn out, (b,s,d)
__device__ float g_x1[(size_t)MTOT*DD];        // post-attention residual
__device__ float g_hh[(size_t)MTOT*DFFF];      // MLP hidden

// ---------------------------------------------------------------------------
// GEMM: C[m,n] = sum_k A[m,k] * W[n,k]   (both K-major), M=8192 fixed.
// 128x128 tile, BK=16, 256 threads, 8x8 per-thread microtile.
// EPI: 0 = scatter to (b,h,s,dk) layout (QKV)
//      1 = 5/6*Res + acc/18           (attention residual, wo)
//      2 = gelu_exact(acc)/1.1289     (MLP up)
//      3 = 5/6*Res + acc/6            (MLP residual, w_down)
// ---------------------------------------------------------------------------
template<int EPI>
__global__ __launch_bounds__(256)
void gemm_kernel(const float* __restrict__ A, const float* __restrict__ W,
                 const float* __restrict__ Res, float* __restrict__ C,
                 int Ndim, int Kdim)
{
    __shared__ float As[16][132];
    __shared__ float Bs[16][132];

    const int t  = threadIdx.x;
    const int bn = blockIdx.x;
    const int bm = blockIdx.y;

    const float* Ap = A + (size_t)bm * 128 * Kdim;
    const float* Wp = W + (size_t)bn * 128 * Kdim;

    const int lr = t >> 2;            // 0..63
    const int lc = (t & 3) << 2;      // 0,4,8,12
    const int m0 = (t >> 4) << 3;     // 0..120
    const int n0 = (t & 15) << 3;     // 0..120

    float acc[8][8];
    #pragma unroll
    for (int i = 0; i < 8; i++)
        #pragma unroll
        for (int j = 0; j < 8; j++) acc[i][j] = 0.f;

    for (int k0 = 0; k0 < Kdim; k0 += 16) {
        float4 a0 = *(const float4*)(Ap + (size_t)lr        * Kdim + k0 + lc);
        float4 a1 = *(const float4*)(Ap + (size_t)(lr + 64) * Kdim + k0 + lc);
        float4 b0 = *(const float4*)(Wp + (size_t)lr        * Kdim + k0 + lc);
        float4 b1 = *(const float4*)(Wp + (size_t)(lr + 64) * Kdim + k0 + lc);

        __syncthreads();
        As[lc+0][lr   ] = a0.x; As[lc+1][lr   ] = a0.y; As[lc+2][lr   ] = a0.z; As[lc+3][lr   ] = a0.w;
        As[lc+0][lr+64] = a1.x; As[lc+1][lr+64] = a1.y; As[lc+2][lr+64] = a1.z; As[lc+3][lr+64] = a1.w;
        Bs[lc+0][lr   ] = b0.x; Bs[lc+1][lr   ] = b0.y; Bs[lc+2][lr   ] = b0.z; Bs[lc+3][lr   ] = b0.w;
        Bs[lc+0][lr+64] = b1.x; Bs[lc+1][lr+64] = b1.y; Bs[lc+2][lr+64] = b1.z; Bs[lc+3][lr+64] = b1.w;
        __syncthreads();

        #pragma unroll
        for (int kk = 0; kk < 16; kk++) {
            float4 av0 = *(const float4*)&As[kk][m0];
            float4 av1 = *(const float4*)&As[kk][m0 + 4];
            float4 bv0 = *(const float4*)&Bs[kk][n0];
            float4 bv1 = *(const float4*)&Bs[kk][n0 + 4];
            const float a[8] = {av0.x, av0.y, av0.z, av0.w, av1.x, av1.y, av1.z, av1.w};
            const float b[8] = {bv0.x, bv0.y, bv0.z, bv0.w, bv1.x, bv1.y, bv1.z, bv1.w};
            #pragma unroll
            for (int i = 0; i < 8; i++)
                #pragma unroll
                for (int j = 0; j < 8; j++)
                    acc[i][j] = fmaf(a[i], b[j], acc[i][j]);
        }
    }

    const int gm0 = bm * 128 + m0;
    const int gn0 = bn * 128 + n0;

    if (EPI == 0) {
        // scatter to (b, h, s, dk): m = b*SS + s ; n = h*DKK + dk
        #pragma unroll
        for (int i = 0; i < 8; i++) {
            const int m    = gm0 + i;
            const int bidx = m >> 12;
            const int s_   = m & (SS - 1);
            #pragma unroll
            for (int j = 0; j < 8; j++) {
                const int n  = gn0 + j;
                const int h  = n >> 6;
                const int dk = n & 63;
                C[((((size_t)bidx * HH + h) * SS + s_) << 6) + dk] = acc[i][j];
            }
        }
    } else if (EPI == 1) {
        #pragma unroll
        for (int i = 0; i < 8; i++) {
            const size_t row = (size_t)(gm0 + i) * DD;
            #pragma unroll
            for (int j = 0; j < 8; j++)
                C[row + gn0 + j] = (5.0f/6.0f) * Res[row + gn0 + j] + acc[i][j] * (1.0f/18.0f);
        }
    } else if (EPI == 2) {
        #pragma unroll
        for (int i = 0; i < 8; i++) {
            const size_t row = (size_t)(gm0 + i) * DFFF;
            #pragma unroll
            for (int j = 0; j < 8; j++) {
                const float u = acc[i][j];
                const float g = 0.5f * u * (1.0f + erff(u * 0.70710678118654752f));
                C[row + gn0 + j] = g * (1.0f / 1.1289f);
            }
        }
    } else { // EPI == 3
        #pragma unroll
        for (int i = 0; i < 8; i++) {
            const size_t row = (size_t)(gm0 + i) * DD;
            #pragma unroll
            for (int j = 0; j < 8; j++)
                C[row + gn0 + j] = (5.0f/6.0f) * Res[row + gn0 + j] + acc[i][j] * (1.0f/6.0f);
        }
    }
}

// ---------------------------------------------------------------------------
// Causal flash attention, fp32. Br = Bc = 64, DK = 64.
// Grid: (S/64, B*H); tiles above the diagonal are skipped entirely.
// ---------------------------------------------------------------------------
#define FPAD 68
#define FLASH_SMEM (4 * 64 * FPAD * sizeof(float))   // 69632 B

__device__ __forceinline__ float rmax16(float v) {
    #pragma unroll
    for (int o = 8; o; o >>= 1) v = fmaxf(v, __shfl_xor_sync(0xffffffffu, v, o));
    return v;
}
__device__ __forceinline__ float rsum16(float v) {
    #pragma unroll
    for (int o = 8; o; o >>= 1) v += __shfl_xor_sync(0xffffffffu, v, o);
    return v;
}

__global__ __launch_bounds__(256)
void flash_kernel(const float* __restrict__ Q, const float* __restrict__ K,
                  const float* __restrict__ V, float* __restrict__ O)
{
    extern __shared__ float fsm[];
    float* Qs = fsm;                 // [dk][row]   64 x FPAD
    float* Ks = fsm + 64 * FPAD;     // [dk][kcol]
    float* Vs = fsm + 2 * 64 * FPAD; // [kcol][dk]
    float* Ps = fsm + 3 * 64 * FPAD; // [row][kcol]

    const int t  = threadIdx.x;
    const int tx = t & 15, ty = t >> 4;
    const int r0 = ty * 4, c0 = tx * 4;

    const int bh   = blockIdx.y;
    const int qt   = gridDim.x - 1 - blockIdx.x;  // heavy blocks first
    const int bidx = bh >> 3;
    const int h    = bh & 7;

    const float* Qb = Q + (size_t)bh * SS * DKK;
    const float* Kb = K + (size_t)bh * SS * DKK;
    const float* Vb = V + (size_t)bh * SS * DKK;

    const int lrow = t >> 2;          // 0..63
    const int lc0  = (t & 3) * 16;    // 0,16,32,48

    // Load Q tile, transposed to [dk][row]
    {
        const float* src = Qb + ((size_t)(qt * 64) + lrow) * 64 + lc0;
        #pragma unroll
        for (int u = 0; u < 4; u++) {
            float4 vv = *(const float4*)(src + u * 4);
            Qs[(lc0 + u*4 + 0) * FPAD + lrow] = vv.x;
            Qs[(lc0 + u*4 + 1) * FPAD + lrow] = vv.y;
            Qs[(lc0 + u*4 + 2) * FPAD + lrow] = vv.z;
            Qs[(lc0 + u*4 + 3) * FPAD + lrow] = vv.w;
        }
    }

    float oacc[4][4];
    float mrow[4], lsum[4];
    #pragma unroll
    for (int i = 0; i < 4; i++) {
        mrow[i] = -3.0e38f; lsum[i] = 0.f;
        #pragma unroll
        for (int j = 0; j < 4; j++) oacc[i][j] = 0.f;
    }

    for (int kt = 0; kt <= qt; kt++) {
        __syncthreads();   // protect Ks/Vs/Ps from previous iteration's readers
        {
            const float* ks = Kb + ((size_t)(kt * 64) + lrow) * 64 + lc0;
            const float* vs = Vb + ((size_t)(kt * 64) + lrow) * 64 + lc0;
            #pragma unroll
            for (int u = 0; u < 4; u++) {
                float4 kv = *(const float4*)(ks + u * 4);
                Ks[(lc0 + u*4 + 0) * FPAD + lrow] = kv.x;
                Ks[(lc0 + u*4 + 1) * FPAD + lrow] = kv.y;
                Ks[(lc0 + u*4 + 2) * FPAD + lrow] = kv.z;
                Ks[(lc0 + u*4 + 3) * FPAD + lrow] = kv.w;
                float4 vv = *(const float4*)(vs + u * 4);
                *(float4*)&Vs[lrow * FPAD + lc0 + u * 4] = vv;
            }
        }
        __syncthreads();

        // S = (Q K^T) / 64
        float sc[4][4];
        #pragma unroll
        for (int i = 0; i < 4; i++)
            #pragma unroll
            for (int j = 0; j < 4; j++) sc[i][j] = 0.f;

        #pragma unroll 16
        for (int kk = 0; kk < 64; kk++) {
            float4 qa = *(const float4*)&Qs[kk * FPAD + r0];
            float4 kb = *(const float4*)&Ks[kk * FPAD + c0];
            const float a[4] = {qa.x, qa.y, qa.z, qa.w};
            const float b[4] = {kb.x, kb.y, kb.z, kb.w};
            #pragma unroll
            for (int i = 0; i < 4; i++)
                #pragma unroll
                for (int j = 0; j < 4; j++)
                    sc[i][j] = fmaf(a[i], b[j], sc[i][j]);
        }

        const bool diag = (kt == qt);
        #pragma unroll
        for (int i = 0; i < 4; i++)
            #pragma unroll
            for (int j = 0; j < 4; j++) {
                float s = sc[i][j] * (1.0f / 64.0f);
                if (diag && (c0 + j > r0 + i)) s = -1e30f;
                sc[i][j] = s;
            }

        // online softmax per row
        #pragma unroll
        for (int i = 0; i < 4; i++) {
            float mt = fmaxf(fmaxf(sc[i][0], sc[i][1]), fmaxf(sc[i][2], sc[i][3]));
            mt = rmax16(mt);
            const float mnew  = fmaxf(mrow[i], mt);
            const float alpha = __expf(mrow[i] - mnew);
            mrow[i] = mnew;
            float rs = 0.f;
            #pragma unroll
            for (int j = 0; j < 4; j++) {
                const float p = __expf(sc[i][j] - mnew);
                sc[i][j] = p; rs += p;
            }
            rs = rsum16(rs);
            lsum[i] = lsum[i] * alpha + rs;
            #pragma unroll
            for (int j = 0; j < 4; j++) oacc[i][j] *= alpha;
            float4 pv = make_float4(sc[i][0], sc[i][1], sc[i][2], sc[i][3]);
            *(float4*)&Ps[(r0 + i) * FPAD + c0] = pv;
        }
        __syncthreads();

        // O += P V
        #pragma unroll 16
        for (int kc = 0; kc < 64; kc++) {
            float4 vb = *(const float4*)&Vs[kc * FPAD + c0];
            const float b[4] = {vb.x, vb.y, vb.z, vb.w};
            #pragma unroll
            for (int i = 0; i < 4; i++) {
                const float a = Ps[(r0 + i) * FPAD + kc];
                #pragma unroll
                for (int j = 0; j < 4; j++)
                    oacc[i][j] = fmaf(a, b[j], oacc[i][j]);
            }
        }
    }

    // normalize + write (b, s, h*64 + dk)
    #pragma unroll
    for (int i = 0; i < 4; i++) {
        const float inv = 1.0f / lsum[i];
        const int srow  = qt * 64 + r0 + i;
        float4 r = make_float4(oacc[i][0] * inv, oacc[i][1] * inv,
                               oacc[i][2] * inv, oacc[i][3] * inv);
        *(float4*)&O[((size_t)bidx * SS + srow) * DD + h * 64 + c0] = r;
    }
}

// ---------------------------------------------------------------------------
// Launch
// ---------------------------------------------------------------------------
extern "C" void kernel_launch(void* const* d_in, const int* in_sizes, int n_in,
                              void* d_out, int out_size)
{
    (void)in_sizes; (void)n_in; (void)out_size;
    const float* x      = (const float*)d_in[0];
    // d_in[1] = mask (int32) — causal, handled analytically
    const float* wq     = (const float*)d_in[2];
    const float* wk     = (const float*)d_in[3];
    const float* wv     = (const float*)d_in[4];
    const float* wo     = (const float*)d_in[5];
    const float* w_up   = (const float*)d_in[6];
    const float* w_down = (const float*)d_in[7];
    float* out = (float*)d_out;

    float *q, *k, *v, *o, *x1, *hh;
    cudaGetSymbolAddress((void**)&q,  g_q);
    cudaGetSymbolAddress((void**)&k,  g_k);
    cudaGetSymbolAddress((void**)&v,  g_v);
    cudaGetSymbolAddress((void**)&o,  g_o);
    cudaGetSymbolAddress((void**)&x1, g_x1);
    cudaGetSymbolAddress((void**)&hh, g_hh);

    cudaFuncSetAttribute(flash_kernel,
                         cudaFuncAttributeMaxDynamicSharedMemorySize,
                         (int)FLASH_SMEM);

    dim3 blk(256);
    // QKV projections (scatter epilogue into (b,h,s,dk))
    gemm_kernel<0><<<dim3(4, 64), blk>>>(x, wq, nullptr, q, DD,  DD);
    gemm_kernel<0><<<dim3(4, 64), blk>>>(x, wk, nullptr, k, DD,  DD);
    gemm_kernel<0><<<dim3(4, 64), blk>>>(x, wv, nullptr, v, DD,  DD);
    // Causal flash attention
    flash_kernel<<<dim3(SS / 64, BB * HH), blk, FLASH_SMEM>>>(q, k, v, o);
    // x1 = 5/6 x + 1/18 (O wo^T)
    gemm_kernel<1><<<dim3(4, 64), blk>>>(o, wo, x, x1, DD, DD);
    // h = gelu(x1 w_up^T)/1.1289
    gemm_kernel<2><<<dim3(16, 64), blk>>>(x1, w_up, nullptr, hh, DFFF, DD);
    // out = 5/6 x1 + 1/6 (h w_down^T)
    gemm_kernel<3><<<dim3(4, 64), blk>>>(hh, w_down, x1, out, DD, DFFF);
}

// round 3
// speedup vs baseline: 3.3885x; 3.3885x over previous
#include <cuda_runtime.h>
#include <cuda_bf16.h>
#include <math.h>
#include <stdint.h>

// Problem constants
#define BB    2
#define SS    4096
#define DD    512
#define HH    8
#define DKK   64
#define DFFF  2048
#define MTOT  (BB*SS)          // 8192 rows

// ---------------------------------------------------------------------------
// Scratch (static device buffers; allocation-free per harness rules)
// ---------------------------------------------------------------------------
__device__ __nv_bfloat16 g_qb[(size_t)BB*HH*SS*DKK];  // bf16 (b,h,s,dk)
__device__ __nv_bfloat16 g_kb[(size_t)BB*HH*SS*DKK];
__device__ __nv_bfloat16 g_vb[(size_t)BB*HH*SS*DKK];
__device__ float g_o [(size_t)MTOT*DD];               // attn out (b,s,d) fp32
__device__ float g_x1[(size_t)MTOT*DD];               // post-attn residual fp32

// split-bf16 buffers (K' = 3K packing)
__device__ __nv_bfloat16 g_xs    [(size_t)MTOT*3*DD];     // x split (act: hi,hi,lo)
__device__ __nv_bfloat16 g_os    [(size_t)MTOT*3*DD];     // attn-out split
__device__ __nv_bfloat16 g_x1s   [(size_t)MTOT*3*DD];     // x1 split
__device__ __nv_bfloat16 g_hs    [(size_t)MTOT*3*DFFF];   // gelu hidden split
__device__ __nv_bfloat16 g_wqkvs [(size_t)3*DD*3*DD];     // [1536,1536] (w: hi,lo,hi)
__device__ __nv_bfloat16 g_wos   [(size_t)DD*3*DD];       // [512,1536]
__device__ __nv_bfloat16 g_wups  [(size_t)DFFF*3*DD];     // [2048,1536]
__device__ __nv_bfloat16 g_wdns  [(size_t)DD*3*DFFF];     // [512,6144]

// ---------------------------------------------------------------------------
// PTX helpers (plain sm_100-compatible: cp.async + ldmatrix + mma.sync)
// ---------------------------------------------------------------------------
__device__ __forceinline__ uint32_t smem_u32(const void* p) {
    uint32_t a;
    asm("{ .reg .u64 t; cvta.to.shared.u64 t, %1; cvt.u32.u64 %0, t; }" : "=r"(a) : "l"(p));
    return a;
}
__device__ __forceinline__ void cp_async16(uint32_t dst, const void* src) {
    asm volatile("cp.async.cg.shared.global [%0], [%1], 16;" :: "r"(dst), "l"(src));
}
__device__ __forceinline__ void cp_commit() {
    asm volatile("cp.async.commit_group;" ::: "memory");
}
template<int N> __device__ __forceinline__ void cp_wait() {
    asm volatile("cp.async.wait_group %0;" :: "n"(N) : "memory");
}

#define LDSM4(r, addr) \
    asm volatile("ldmatrix.sync.aligned.m8n8.x4.shared.b16 {%0,%1,%2,%3}, [%4];" \
        : "=r"((r)[0]), "=r"((r)[1]), "=r"((r)[2]), "=r"((r)[3]) : "r"(addr))
#define LDSM2(r, addr) \
    asm volatile("ldmatrix.sync.aligned.m8n8.x2.shared.b16 {%0,%1}, [%2];" \
        : "=r"((r)[0]), "=r"((r)[1]) : "r"(addr))
#define LDSM2T(r, addr) \
    asm volatile("ldmatrix.sync.aligned.m8n8.x2.trans.shared.b16 {%0,%1}, [%2];" \
        : "=r"((r)[0]), "=r"((r)[1]) : "r"(addr))
#define MMA_BF16(d, a, b) \
    asm volatile("mma.sync.aligned.m16n8k16.row.col.f32.bf16.bf16.f32 " \
        "{%0,%1,%2,%3}, {%4,%5,%6,%7}, {%8,%9}, {%0,%1,%2,%3};" \
        : "+f"((d)[0]), "+f"((d)[1]), "+f"((d)[2]), "+f"((d)[3]) \
        : "r"((a)[0]), "r"((a)[1]), "r"((a)[2]), "r"((a)[3]), "r"((b)[0]), "r"((b)[1]))

__device__ __forceinline__ uint32_t pack_bf2(float lo, float hi) {
    __nv_bfloat162 t = __floats2bfloat162_rn(lo, hi);
    return *reinterpret_cast<uint32_t*>(&t);
}

// write (hi,hi,lo) act-split pair at [col], [C+col], [2C+col]
__device__ __forceinline__ void write_split2(__nv_bfloat16* rowp, int col, int C,
                                             float v0, float v1) {
    __nv_bfloat162 h = __floats2bfloat162_rn(v0, v1);
    float l0 = v0 - __bfloat162float(h.x);
    float l1 = v1 - __bfloat162float(h.y);
    __nv_bfloat162 l = __floats2bfloat162_rn(l0, l1);
    *(__nv_bfloat162*)(rowp + col)         = h;
    *(__nv_bfloat162*)(rowp + C + col)     = h;
    *(__nv_bfloat162*)(rowp + 2 * C + col) = l;
}

// ---------------------------------------------------------------------------
// Split kernels: fp32 [R,C] -> bf16 [R,3C]
// MODE 0 (act): hi, hi, lo ; MODE 1 (weight): hi, lo, hi
// ---------------------------------------------------------------------------
template<int MODE>
__global__ __launch_bounds__(256)
void split_kernel(const float* __restrict__ src, __nv_bfloat16* __restrict__ dst,
                  int C, int total)
{
    int i4 = (blockIdx.x * 256 + threadIdx.x) * 4;
    if (i4 >= total) return;
    int r = i4 / C, c = i4 % C;
    float4 xv = *(const float4*)(src + (size_t)r * C + c);
    __nv_bfloat162 h01 = __floats2bfloat162_rn(xv.x, xv.y);
    __nv_bfloat162 h23 = __floats2bfloat162_rn(xv.z, xv.w);
    __nv_bfloat162 l01 = __floats2bfloat162_rn(xv.x - __bfloat162float(h01.x),
                                               xv.y - __bfloat162float(h01.y));
    __nv_bfloat162 l23 = __floats2bfloat162_rn(xv.z - __bfloat162float(h23.x),
                                               xv.w - __bfloat162float(h23.y));
    uint2 hv = make_uint2(*(uint32_t*)&h01, *(uint32_t*)&h23);
    uint2 lv = make_uint2(*(uint32_t*)&l01, *(uint32_t*)&l23);
    size_t base = (size_t)r * 3 * C;
    *reinterpret_cast<uint2*>(dst + base + c) = hv;
    if (MODE == 0) {
        *reinterpret_cast<uint2*>(dst + base + C + c)     = hv;
        *reinterpret_cast<uint2*>(dst + base + 2 * C + c) = lv;
    } else {
        *reinterpret_cast<uint2*>(dst + base + C + c)     = lv;
        *reinterpret_cast<uint2*>(dst + base + 2 * C + c) = hv;
    }
}

// ---------------------------------------------------------------------------
// HMMA GEMM: C[m,n] = sum_k A[m,k] * W[n,k]  (bf16 in, fp32 accum), M=8192.
// 128x128 tile, BK=64 halves, 8 warps (2m x 4n), 3-stage cp.async pipeline.
// EPI: 0 = write bf16 q/k/v scatter to (b,h,s,dk)  (N=1536)
//      1 = x1 = 5/6 res + acc/18 (fp32) + act-split -> b0
//      2 = gelu(acc)/1.1289 act-split -> b0 (C=2048)
//      3 = out = 5/6 res + acc/6 (fp32)
// ---------------------------------------------------------------------------
#define GSTAGE 36864
#define GSMEM  (3 * GSTAGE)   // 110592

template<int EPI>
__global__ __launch_bounds__(256)
void gemm_hmma(const __nv_bfloat16* __restrict__ A, const __nv_bfloat16* __restrict__ W,
               int Kp, float* __restrict__ fo, const float* __restrict__ res,
               __nv_bfloat16* __restrict__ b0, __nv_bfloat16* __restrict__ b1,
               __nv_bfloat16* __restrict__ b2)
{
    extern __shared__ char smem[];
    const uint32_t sb = smem_u32(smem);
    const int tid = threadIdx.x, wid = tid >> 5, lane = tid & 31;
    const int bn = blockIdx.x, bm = blockIdx.y;
    const int wm = wid & 1, wn = wid >> 1;

    float acc[4][4][4];
    #pragma unroll
    for (int mi = 0; mi < 4; mi++)
        #pragma unroll
        for (int ni = 0; ni < 4; ni++)
            #pragma unroll
            for (int c = 0; c < 4; c++) acc[mi][ni][c] = 0.f;

    auto load_chunk = [&](int c, int st) {
        const uint32_t base = sb + (uint32_t)st * GSTAGE;
        #pragma unroll
        for (int u = 0; u < 8; u++) {
            int seg = tid + u * 256;         // 0..2047
            int isB = seg >> 10;
            int r   = (seg >> 3) & 127;
            int sc  = seg & 7;
            const __nv_bfloat16* src = isB ? W : A;
            int rowg = (isB ? bn : bm) * 128 + r;
            const char* g = (const char*)(src + (size_t)rowg * Kp + c * 64) + sc * 16;
            uint32_t d = base + (isB ? 18432u : 0u) + (uint32_t)(r * 144 + sc * 16);
            cp_async16(d, g);
        }
    };

    load_chunk(0, 0); cp_commit();
    load_chunk(1, 1); cp_commit();

    const int nch = Kp >> 6;
    for (int i = 0; i < nch; i++) {
        cp_wait<1>();
        __syncthreads();
        {
            const uint32_t As = sb + (uint32_t)(i % 3) * GSTAGE;
            const uint32_t Bs = As + 18432u;
            #pragma unroll
            for (int ks = 0; ks < 4; ks++) {
                uint32_t a[4][4], b[4][2];
                #pragma unroll
                for (int mi = 0; mi < 4; mi++)
                    LDSM4(a[mi], As + (uint32_t)((wm*64 + mi*16 + (lane & 15)) * 144
                                                 + ks*32 + (lane >> 4) * 16));
                #pragma unroll
                for (int ni = 0; ni < 4; ni++)
                    LDSM2(b[ni], Bs + (uint32_t)((wn*32 + ni*8 + (lane & 7)) * 144
                                                 + ks*32 + ((lane >> 3) & 1) * 16));
                #pragma unroll
                for (int mi = 0; mi < 4; mi++)
                    #pragma unroll
                    for (int ni = 0; ni < 4; ni++)
                        MMA_BF16(acc[mi][ni], a[mi], b[ni]);
            }
        }
        __syncthreads();
        if (i + 2 < nch) load_chunk(i + 2, (i + 2) % 3);
        cp_commit();
    }

    // epilogue straight from registers
    #pragma unroll
    for (int mi = 0; mi < 4; mi++) {
        #pragma unroll
        for (int half = 0; half < 2; half++) {
            const int rg = bm*128 + wm*64 + mi*16 + (lane >> 2) + half*8;
            #pragma unroll
            for (int ni = 0; ni < 4; ni++) {
                const int cg = bn*128 + wn*32 + ni*8 + (lane & 3) * 2;
                float v0 = acc[mi][ni][half*2 + 0];
                float v1 = acc[mi][ni][half*2 + 1];
                if (EPI == 0) {
                    const int which = cg >> 9, h = (cg >> 6) & 7, dk = cg & 63;
                    const int bb = rg >> 12, s = rg & (SS - 1);
                    __nv_bfloat16* dst = (which == 0) ? b0 : ((which == 1) ? b1 : b2);
                    *(__nv_bfloat162*)&dst[((size_t)(bb*HH + h) * SS + s) * 64 + dk] =
                        __floats2bfloat162_rn(v0, v1);
                } else if (EPI == 1) {
                    const float2 xr = *(const float2*)&res[(size_t)rg * DD + cg];
                    float u0 = (5.0f/6.0f) * xr.x + v0 * (1.0f/18.0f);
                    float u1 = (5.0f/6.0f) * xr.y + v1 * (1.0f/18.0f);
                    *(float2*)&fo[(size_t)rg * DD + cg] = make_float2(u0, u1);
                    write_split2(b0 + (size_t)rg * (3*DD), cg, DD, u0, u1);
                } else if (EPI == 2) {
                    float g0 = 0.5f * v0 * (1.0f + erff(v0 * 0.70710678118654752f)) * (1.0f/1.1289f);
                    float g1 = 0.5f * v1 * (1.0f + erff(v1 * 0.70710678118654752f)) * (1.0f/1.1289f);
                    write_split2(b0 + (size_t)rg * (3*DFFF), cg, DFFF, g0, g1);
                } else {
                    const float2 xr = *(const float2*)&res[(size_t)rg * DD + cg];
                    *(float2*)&fo[(size_t)rg * DD + cg] =
                        make_float2((5.0f/6.0f) * xr.x + v0 * (1.0f/6.0f),
                                    (5.0f/6.0f) * xr.y + v1 * (1.0f/6.0f));
                }
            }
        }
    }
}

// ---------------------------------------------------------------------------
// HMMA causal flash attention. CTA = 128 q-rows, 8 warps (one m16 each),
// KV tile 64, DK=64, bf16 operands, fp32 softmax/accum. Double-buffered K/V.
// ---------------------------------------------------------------------------
#define FQ_BYTES   18432              // 128 x 72 halves
#define FKV_STAGE  18432              // (64 + 64) x 72 halves
#define FSMEM      (FQ_BYTES + 2 * FKV_STAGE)   // 55296

__global__ __launch_bounds__(256)
void flash_hmma(const __nv_bfloat16* __restrict__ Q, const __nv_bfloat16* __restrict__ K,
                const __nv_bfloat16* __restrict__ V, float* __restrict__ O)
{
    extern __shared__ char smem[];
    const uint32_t sb = smem_u32(smem);
    const int tid = threadIdx.x, wid = tid >> 5, lane = tid & 31;

    const int bh = blockIdx.y;
    const int qt = gridDim.x - 1 - blockIdx.x;    // heavy tiles first
    const int bidx = bh >> 3, h = bh & 7;

    const __nv_bfloat16* Qb = Q + (size_t)bh * SS * DKK;
    const __nv_bfloat16* Kb = K + (size_t)bh * SS * DKK;
    const __nv_bfloat16* Vb = V + (size_t)bh * SS * DKK;

    // ---- load Q tile (128 x 64) ----
    {
        #pragma unroll
        for (int u = 0; u < 4; u++) {
            int seg = tid + u * 256;           // 0..1023
            int r   = seg >> 3;
            int sc  = seg & 7;
            const char* g = (const char*)(Qb + ((size_t)(qt*128 + r)) * 64) + sc * 16;
            cp_async16(sb + (uint32_t)(r * 144 + sc * 16), g);
        }
        cp_commit();
    }

    auto loadKV = [&](int t, int st) {
        const uint32_t base = sb + FQ_BYTES + (uint32_t)st * FKV_STAGE;
        #pragma unroll
        for (int u = 0; u < 4; u++) {
            int seg = tid + u * 256;           // 0..1023
            int isV = seg >> 9;
            int r   = (seg >> 3) & 63;
            int sc  = seg & 7;
            const __nv_bfloat16* src = isV ? Vb : Kb;
            const char* g = (const char*)(src + ((size_t)(t*64 + r)) * 64) + sc * 16;
            cp_async16(base + (isV ? 9216u : 0u) + (uint32_t)(r * 144 + sc * 16), g);
        }
    };

    const int nkv = 2 * qt + 2;
    loadKV(0, 0); cp_commit();
    loadKV(1, 1); cp_commit();

    // Q fragments in registers for the entire kernel
    cp_wait<2>();
    __syncthreads();
    uint32_t qf[4][4];
    #pragma unroll
    for (int kc = 0; kc < 4; kc++)
        LDSM4(qf[kc], sb + (uint32_t)((wid*16 + (lane & 15)) * 144
                                      + kc*32 + (lane >> 4) * 16));

    float oacc[8][4];
    #pragma unroll
    for (int ni = 0; ni < 8; ni++)
        #pragma unroll
        for (int c = 0; c < 4; c++) oacc[ni][c] = 0.f;
    float m0 = -1e30f, m1 = -1e30f, l0 = 0.f, l1 = 0.f;

    const int rowA = qt*128 + wid*16 + (lane >> 2);   // row of c0/c1; +8 for c2/c3

    for (int kt = 0; kt < nkv; kt++) {
        cp_wait<1>();
        __syncthreads();
        const uint32_t Ks = sb + FQ_BYTES + (uint32_t)(kt & 1) * FKV_STAGE;
        const uint32_t Vs = Ks + 9216u;

        // S = Q K^T
        float sacc[8][4];
        #pragma unroll
        for (int ni = 0; ni < 8; ni++)
            #pragma unroll
            for (int c = 0; c < 4; c++) sacc[ni][c] = 0.f;
        #pragma unroll
        for (int kc = 0; kc < 4; kc++) {
            #pragma unroll
            for (int ni = 0; ni < 8; ni++) {
                uint32_t bb[2];
                LDSM2(bb, Ks + (uint32_t)((ni*8 + (lane & 7)) * 144
                                          + kc*32 + ((lane >> 3) & 1) * 16));
                MMA_BF16(sacc[ni], qf[kc], bb);
            }
        }

        // scale + causal mask
        const bool needMask = (kt >= 2*qt);
        #pragma unroll
        for (int ni = 0; ni < 8; ni++) {
            const int cb = kt*64 + ni*8 + (lane & 3) * 2;
            #pragma unroll
            for (int c = 0; c < 4; c++) {
                float s = sacc[ni][c] * (1.0f / 64.0f);
                if (needMask) {
                    const int row = rowA + ((c >> 1) << 3);
                    const int col = cb + (c & 1);
                    if (col > row) s = -1e30f;
                }
                sacc[ni][c] = s;
            }
        }

        // online softmax (rows rowA and rowA+8); quad-wide reductions
        float mx0 = -1e30f, mx1 = -1e30f;
        #pragma unroll
        for (int ni = 0; ni < 8; ni++) {
            mx0 = fmaxf(mx0, fmaxf(sacc[ni][0], sacc[ni][1]));
            mx1 = fmaxf(mx1, fmaxf(sacc[ni][2], sacc[ni][3]));
        }
        mx0 = fmaxf(mx0, __shfl_xor_sync(0xffffffffu, mx0, 1));
        mx0 = fmaxf(mx0, __shfl_xor_sync(0xffffffffu, mx0, 2));
        mx1 = fmaxf(mx1, __shfl_xor_sync(0xffffffffu, mx1, 1));
        mx1 = fmaxf(mx1, __shfl_xor_sync(0xffffffffu, mx1, 2));
        const float mn0 = fmaxf(m0, mx0), mn1 = fmaxf(m1, mx1);
        const float al0 = __expf(m0 - mn0), al1 = __expf(m1 - mn1);
        m0 = mn0; m1 = mn1;

        float rs0 = 0.f, rs1 = 0.f;
        #pragma unroll
        for (int ni = 0; ni < 8; ni++) {
            sacc[ni][0] = __expf(sacc[ni][0] - mn0);
            sacc[ni][1] = __expf(sacc[ni][1] - mn0);
            sacc[ni][2] = __expf(sacc[ni][2] - mn1);
            sacc[ni][3] = __expf(sacc[ni][3] - mn1);
            rs0 += sacc[ni][0] + sacc[ni][1];
            rs1 += sacc[ni][2] + sacc[ni][3];
        }
        rs0 += __shfl_xor_sync(0xffffffffu, rs0, 1);
        rs0 += __shfl_xor_sync(0xffffffffu, rs0, 2);
        rs1 += __shfl_xor_sync(0xffffffffu, rs1, 1);
        rs1 += __shfl_xor_sync(0xffffffffu, rs1, 2);
        l0 = l0 * al0 + rs0;
        l1 = l1 * al1 + rs1;
        #pragma unroll
        for (int ni = 0; ni < 8; ni++) {
            oacc[ni][0] *= al0; oacc[ni][1] *= al0;
            oacc[ni][2] *= al1; oacc[ni][3] *= al1;
        }

        // pack P (C-frag -> A-frag layout)
        uint32_t pf[4][4];
        #pragma unroll
        for (int kc = 0; kc < 4; kc++) {
            pf[kc][0] = pack_bf2(sacc[2*kc][0],   sacc[2*kc][1]);
            pf[kc][1] = pack_bf2(sacc[2*kc][2],   sacc[2*kc][3]);
            pf[kc][2] = pack_bf2(sacc[2*kc+1][0], sacc[2*kc+1][1]);
            pf[kc][3] = pack_bf2(sacc[2*kc+1][2], sacc[2*kc+1][3]);
        }

        // O += P V   (V via ldmatrix.trans)
        #pragma unroll
        for (int kc = 0; kc < 4; kc++) {
            #pragma unroll
            for (int ni = 0; ni < 8; ni++) {
                uint32_t bv[2];
                LDSM2T(bv, Vs + (uint32_t)((kc*16 + (lane & 15)) * 144 + ni * 16));
                MMA_BF16(oacc[ni], pf[kc], bv);
            }
        }

        __syncthreads();
        if (kt + 2 < nkv) loadKV(kt + 2, kt & 1);
        cp_commit();
    }

    // normalize + write O (b, s, h*64+dk) fp32
    const float inv0 = 1.0f / l0, inv1 = 1.0f / l1;
    #pragma unroll
    for (int half = 0; half < 2; half++) {
        const int rg = qt*128 + wid*16 + (lane >> 2) + half*8;
        const float inv = half ? inv1 : inv0;
        #pragma unroll
        for (int ni = 0; ni < 8; ni++) {
            const int dk = ni*8 + (lane & 3) * 2;
            *(float2*)&O[((size_t)bidx * SS + rg) * DD + h*64 + dk] =
                make_float2(oacc[ni][half*2] * inv, oacc[ni][half*2 + 1] * inv);
        }
    }
}

// ---------------------------------------------------------------------------
// Launch
// ---------------------------------------------------------------------------
extern "C" void kernel_launch(void* const* d_in, const int* in_sizes, int n_in,
                              void* d_out, int out_size)
{
    (void)in_sizes; (void)n_in; (void)out_size;
    const float* x      = (const float*)d_in[0];
    const float* wq     = (const float*)d_in[2];
    const float* wk     = (const float*)d_in[3];
    const float* wv     = (const float*)d_in[4];
    const float* wo     = (const float*)d_in[5];
    const float* w_up   = (const float*)d_in[6];
    const float* w_down = (const float*)d_in[7];
    float* out = (float*)d_out;

    float *o, *x1;
    __nv_bfloat16 *qb, *kb, *vb, *xs, *os, *x1s, *hs, *wqkvs, *wos, *wups, *wdns;
    cudaGetSymbolAddress((void**)&qb, g_qb);
    cudaGetSymbolAddress((void**)&kb, g_kb);
    cudaGetSymbolAddress((void**)&vb, g_vb);
    cudaGetSymbolAddress((void**)&o,  g_o);
    cudaGetSymbolAddress((void**)&x1, g_x1);
    cudaGetSymbolAddress((void**)&xs,    g_xs);
    cudaGetSymbolAddress((void**)&os,    g_os);
    cudaGetSymbolAddress((void**)&x1s,   g_x1s);
    cudaGetSymbolAddress((void**)&hs,    g_hs);
    cudaGetSymbolAddress((void**)&wqkvs, g_wqkvs);
    cudaGetSymbolAddress((void**)&wos,   g_wos);
    cudaGetSymbolAddress((void**)&wups,  g_wups);
    cudaGetSymbolAddress((void**)&wdns,  g_wdns);

    cudaFuncSetAttribute(flash_hmma,   cudaFuncAttributeMaxDynamicSharedMemorySize, FSMEM);
    cudaFuncSetAttribute(gemm_hmma<0>, cudaFuncAttributeMaxDynamicSharedMemorySize, GSMEM);
    cudaFuncSetAttribute(gemm_hmma<1>, cudaFuncAttributeMaxDynamicSharedMemorySize, GSMEM);
    cudaFuncSetAttribute(gemm_hmma<2>, cudaFuncAttributeMaxDynamicSharedMemorySize, GSMEM);
    cudaFuncSetAttribute(gemm_hmma<3>, cudaFuncAttributeMaxDynamicSharedMemorySize, GSMEM);

    dim3 blk(256);

    // splits: activations (hi,hi,lo), weights (hi,lo,hi)
    split_kernel<0><<<MTOT*DD/4/256, blk>>>(x, xs, DD, MTOT*DD);
    split_kernel<1><<<DD*DD/4/256, blk>>>(wq, wqkvs,                     DD, DD*DD);
    split_kernel<1><<<DD*DD/4/256, blk>>>(wk, wqkvs + (size_t)DD*3*DD,   DD, DD*DD);
    split_kernel<1><<<DD*DD/4/256, blk>>>(wv, wqkvs + (size_t)2*DD*3*DD, DD, DD*DD);
    split_kernel<1><<<DD*DD/4/256, blk>>>(wo, wos,                       DD, DD*DD);
    split_kernel<1><<<DFFF*DD/4/256, blk>>>(w_up, wups,                  DD, DFFF*DD);
    split_kernel<1><<<DD*DFFF/4/256, blk>>>(w_down, wdns,                DFFF, DD*DFFF);

    // fused QKV projection (N=1536) -> bf16 q,k,v (b,h,s,dk)
    gemm_hmma<0><<<dim3(12, 64), blk, GSMEM>>>(xs, wqkvs, 3*DD, nullptr, nullptr, qb, kb, vb);

    // causal flash attention (bf16 HMMA)
    flash_hmma<<<dim3(SS/128, BB*HH), blk, FSMEM>>>(qb, kb, vb, o);

    // split attn output
    split_kernel<0><<<MTOT*DD/4/256, blk>>>(o, os, DD, MTOT*DD);

    // x1 = 5/6 x + 1/18 (O wo^T) (+ split)
    gemm_hmma<1><<<dim3(4, 64), blk, GSMEM>>>(os, wos, 3*DD, x1, x, x1s, nullptr, nullptr);

    // h = gelu(x1 w_up^T)/1.1289 (split direct)
    gemm_hmma<2><<<dim3(16, 64), blk, GSMEM>>>(x1s, wups, 3*DD, nullptr, nullptr, hs, nullptr, nullptr);

    // out = 5/6 x1 + 1/6 (h w_down^T)
    gemm_hmma<3><<<dim3(4, 64), blk, GSMEM>>>(hs, wdns, 3*DFFF, out, x1, nullptr, nullptr, nullptr);
}

// round 4
// speedup vs baseline: 6.3162x; 1.8640x over previous
#include <cuda_runtime.h>
#include <cuda_fp16.h>
#include <math.h>
#include <stdint.h>

// Problem constants
#define BB    2
#define SS    4096
#define DD    512
#define HH    8
#define DKK   64
#define DFFF  2048
#define MTOT  (BB*SS)          // 8192 rows

// ---------------------------------------------------------------------------
// Scratch (static device buffers; allocation-free per harness rules)
// ---------------------------------------------------------------------------
__device__ __half g_qh[(size_t)BB*HH*SS*DKK];   // (b,h,s,dk) fp16
__device__ __half g_kh[(size_t)BB*HH*SS*DKK];
__device__ __half g_vh[(size_t)BB*HH*SS*DKK];
__device__ __half g_oh[(size_t)MTOT*DD];        // attn out (b,s,d) fp16
__device__ float  g_x1[(size_t)MTOT*DD];        // post-attn residual fp32
__device__ __half g_x1h[(size_t)MTOT*DD];       // x1 fp16
__device__ __half g_hh [(size_t)MTOT*DFFF];     // gelu hidden fp16
__device__ __half g_xh [(size_t)MTOT*DD];       // x fp16
__device__ __half g_wqkvh[(size_t)3*DD*DD];     // [1536,512]
__device__ __half g_woh  [(size_t)DD*DD];       // [512,512]
__device__ __half g_wuph [(size_t)DFFF*DD];     // [2048,512]
__device__ __half g_wdnh [(size_t)DD*DFFF];     // [512,2048]

// ---------------------------------------------------------------------------
// PTX helpers (plain sm_100-compatible: cp.async + ldmatrix + mma.sync)
// ---------------------------------------------------------------------------
__device__ __forceinline__ uint32_t smem_u32(const void* p) {
    uint32_t a;
    asm("{ .reg .u64 t; cvta.to.shared.u64 t, %1; cvt.u32.u64 %0, t; }" : "=r"(a) : "l"(p));
    return a;
}
__device__ __forceinline__ void cp_async16(uint32_t dst, const void* src) {
    asm volatile("cp.async.cg.shared.global [%0], [%1], 16;" :: "r"(dst), "l"(src));
}
__device__ __forceinline__ void cp_commit() {
    asm volatile("cp.async.commit_group;" ::: "memory");
}
template<int N> __device__ __forceinline__ void cp_wait() {
    asm volatile("cp.async.wait_group %0;" :: "n"(N) : "memory");
}

#define LDSM4(r, addr) \
    asm volatile("ldmatrix.sync.aligned.m8n8.x4.shared.b16 {%0,%1,%2,%3}, [%4];" \
        : "=r"((r)[0]), "=r"((r)[1]), "=r"((r)[2]), "=r"((r)[3]) : "r"(addr))
#define LDSM2(r, addr) \
    asm volatile("ldmatrix.sync.aligned.m8n8.x2.shared.b16 {%0,%1}, [%2];" \
        : "=r"((r)[0]), "=r"((r)[1]) : "r"(addr))
#define LDSM2T(r, addr) \
    asm volatile("ldmatrix.sync.aligned.m8n8.x2.trans.shared.b16 {%0,%1}, [%2];" \
        : "=r"((r)[0]), "=r"((r)[1]) : "r"(addr))
#define MMA_F16(d, a, b) \
    asm volatile("mma.sync.aligned.m16n8k16.row.col.f32.f16.f16.f32 " \
        "{%0,%1,%2,%3}, {%4,%5,%6,%7}, {%8,%9}, {%0,%1,%2,%3};" \
        : "+f"((d)[0]), "+f"((d)[1]), "+f"((d)[2]), "+f"((d)[3]) \
        : "r"((a)[0]), "r"((a)[1]), "r"((a)[2]), "r"((a)[3]), "r"((b)[0]), "r"((b)[1]))

__device__ __forceinline__ uint32_t pack_h2(float a, float b) {
    __half2 t = __floats2half2_rn(a, b);
    return *reinterpret_cast<uint32_t*>(&t);
}

// ---------------------------------------------------------------------------
// fp32 -> fp16 convert, 4 elements / thread
// ---------------------------------------------------------------------------
__global__ __launch_bounds__(256)
void tohalf_kernel(const float* __restrict__ src, __half* __restrict__ dst, int total)
{
    int i4 = (blockIdx.x * 256 + threadIdx.x) * 4;
    if (i4 >= total) return;
    float4 v = *(const float4*)(src + i4);
    __half2 a = __floats2half2_rn(v.x, v.y);
    __half2 b = __floats2half2_rn(v.z, v.w);
    *reinterpret_cast<uint2*>(dst + i4) =
        make_uint2(*(uint32_t*)&a, *(uint32_t*)&b);
}

// ---------------------------------------------------------------------------
// HMMA GEMM: C[m,n] = sum_k A[m,k] * W[n,k]  (fp16 in, fp32 accum), M=8192.
// 128x128 tile, BK=64 halves, 8 warps (2m x 4n), 3-stage cp.async pipeline.
// EPI: 0 = write fp16 q/k/v scatter to (b,h,s,dk)  (N=1536)
//      1 = x1 = 5/6 res + acc/18 -> fp32 fo and fp16 h0
//      2 = gelu(acc)/1.1289 -> fp16 h0 (C=2048)
//      3 = out = 5/6 res + acc/6 -> fp32 fo
// ---------------------------------------------------------------------------
#define GSTAGE 36864
#define GSMEM  (3 * GSTAGE)   // 110592

template<int EPI>
__global__ __launch_bounds__(256)
void gemm_hmma(const __half* __restrict__ A, const __half* __restrict__ W,
               int Kp, float* __restrict__ fo, const float* __restrict__ res,
               __half* __restrict__ h0, __half* __restrict__ h1,
               __half* __restrict__ h2)
{
    extern __shared__ char smem[];
    const uint32_t sb = smem_u32(smem);
    const int tid = threadIdx.x, wid = tid >> 5, lane = tid & 31;
    const int bn = blockIdx.x, bm = blockIdx.y;
    const int wm = wid & 1, wn = wid >> 1;

    float acc[4][4][4];
    #pragma unroll
    for (int mi = 0; mi < 4; mi++)
        #pragma unroll
        for (int ni = 0; ni < 4; ni++)
            #pragma unroll
            for (int c = 0; c < 4; c++) acc[mi][ni][c] = 0.f;

    auto load_chunk = [&](int c, int st) {
        const uint32_t base = sb + (uint32_t)st * GSTAGE;
        #pragma unroll
        for (int u = 0; u < 8; u++) {
            int seg = tid + u * 256;         // 0..2047
            int isB = seg >> 10;
            int r   = (seg >> 3) & 127;
            int sc  = seg & 7;
            const __half* src = isB ? W : A;
            int rowg = (isB ? bn : bm) * 128 + r;
            const char* g = (const char*)(src + (size_t)rowg * Kp + c * 64) + sc * 16;
            uint32_t d = base + (isB ? 18432u : 0u) + (uint32_t)(r * 144 + sc * 16);
            cp_async16(d, g);
        }
    };

    load_chunk(0, 0); cp_commit();
    load_chunk(1, 1); cp_commit();

    const int nch = Kp >> 6;
    for (int i = 0; i < nch; i++) {
        cp_wait<1>();
        __syncthreads();
        {
            const uint32_t As = sb + (uint32_t)(i % 3) * GSTAGE;
            const uint32_t Bs = As + 18432u;
            #pragma unroll
            for (int ks = 0; ks < 4; ks++) {
                uint32_t a[4][4], b[4][2];
                #pragma unroll
                for (int mi = 0; mi < 4; mi++)
                    LDSM4(a[mi], As + (uint32_t)((wm*64 + mi*16 + (lane & 15)) * 144
                                                 + ks*32 + (lane >> 4) * 16));
                #pragma unroll
                for (int ni = 0; ni < 4; ni++)
                    LDSM2(b[ni], Bs + (uint32_t)((wn*32 + ni*8 + (lane & 7)) * 144
                                                 + ks*32 + ((lane >> 3) & 1) * 16));
                #pragma unroll
                for (int mi = 0; mi < 4; mi++)
                    #pragma unroll
                    for (int ni = 0; ni < 4; ni++)
                        MMA_F16(acc[mi][ni], a[mi], b[ni]);
            }
        }
        __syncthreads();
        if (i + 2 < nch) load_chunk(i + 2, (i + 2) % 3);
        cp_commit();
    }

    // epilogue straight from registers
    #pragma unroll
    for (int mi = 0; mi < 4; mi++) {
        #pragma unroll
        for (int half = 0; half < 2; half++) {
            const int rg = bm*128 + wm*64 + mi*16 + (lane >> 2) + half*8;
            #pragma unroll
            for (int ni = 0; ni < 4; ni++) {
                const int cg = bn*128 + wn*32 + ni*8 + (lane & 3) * 2;
                float v0 = acc[mi][ni][half*2 + 0];
                float v1 = acc[mi][ni][half*2 + 1];
                if (EPI == 0) {
                    const int which = cg >> 9, h = (cg >> 6) & 7, dk = cg & 63;
                    const int bb = rg >> 12, s = rg & (SS - 1);
                    __half* dst = (which == 0) ? h0 : ((which == 1) ? h1 : h2);
                    __half2 hv = __floats2half2_rn(v0, v1);
                    *(__half2*)&dst[((size_t)(bb*HH + h) * SS + s) * 64 + dk] = hv;
                } else if (EPI == 1) {
                    const float2 xr = *(const float2*)&res[(size_t)rg * DD + cg];
                    float u0 = (5.0f/6.0f) * xr.x + v0 * (1.0f/18.0f);
                    float u1 = (5.0f/6.0f) * xr.y + v1 * (1.0f/18.0f);
                    *(float2*)&fo[(size_t)rg * DD + cg] = make_float2(u0, u1);
                    *(__half2*)&h0[(size_t)rg * DD + cg] = __floats2half2_rn(u0, u1);
                } else if (EPI == 2) {
                    float g0 = 0.5f * v0 * (1.0f + erff(v0 * 0.70710678118654752f)) * (1.0f/1.1289f);
                    float g1 = 0.5f * v1 * (1.0f + erff(v1 * 0.70710678118654752f)) * (1.0f/1.1289f);
                    *(__half2*)&h0[(size_t)rg * DFFF + cg] = __floats2half2_rn(g0, g1);
                } else {
                    const float2 xr = *(const float2*)&res[(size_t)rg * DD + cg];
                    *(float2*)&fo[(size_t)rg * DD + cg] =
                        make_float2((5.0f/6.0f) * xr.x + v0 * (1.0f/6.0f),
                                    (5.0f/6.0f) * xr.y + v1 * (1.0f/6.0f));
                }
            }
        }
    }
}

// ---------------------------------------------------------------------------
// HMMA causal flash attention. CTA = 128 q-rows, 8 warps (one m16 each),
// KV tile 64, DK=64, fp16 operands, fp32 softmax/accum. Double-buffered K/V.
// ---------------------------------------------------------------------------
#define FQ_BYTES   18432              // 128 x 72 halves
#define FKV_STAGE  18432              // (64 + 64) x 72 halves
#define FSMEM      (FQ_BYTES + 2 * FKV_STAGE)   // 55296

__global__ __launch_bounds__(256)
void flash_hmma(const __half* __restrict__ Q, const __half* __restrict__ K,
                const __half* __restrict__ V, __half* __restrict__ O)
{
    extern __shared__ char smem[];
    const uint32_t sb = smem_u32(smem);
    const int tid = threadIdx.x, wid = tid >> 5, lane = tid & 31;

    const int bh = blockIdx.y;
    const int qt = gridDim.x - 1 - blockIdx.x;    // heavy tiles first
    const int bidx = bh >> 3, h = bh & 7;

    const __half* Qb = Q + (size_t)bh * SS * DKK;
    const __half* Kb = K + (size_t)bh * SS * DKK;
    const __half* Vb = V + (size_t)bh * SS * DKK;

    // ---- load Q tile (128 x 64) ----
    {
        #pragma unroll
        for (int u = 0; u < 4; u++) {
            int seg = tid + u * 256;           // 0..1023
            int r   = seg >> 3;
            int sc  = seg & 7;
            const char* g = (const char*)(Qb + ((size_t)(qt*128 + r)) * 64) + sc * 16;
            cp_async16(sb + (uint32_t)(r * 144 + sc * 16), g);
        }
        cp_commit();
    }

    auto loadKV = [&](int t, int st) {
        const uint32_t base = sb + FQ_BYTES + (uint32_t)st * FKV_STAGE;
        #pragma unroll
        for (int u = 0; u < 4; u++) {
            int seg = tid + u * 256;           // 0..1023
            int isV = seg >> 9;
            int r   = (seg >> 3) & 63;
            int sc  = seg & 7;
            const __half* src = isV ? Vb : Kb;
            const char* g = (const char*)(src + ((size_t)(t*64 + r)) * 64) + sc * 16;
            cp_async16(base + (isV ? 9216u : 0u) + (uint32_t)(r * 144 + sc * 16), g);
        }
    };

    const int nkv = 2 * qt + 2;
    loadKV(0, 0); cp_commit();
    loadKV(1, 1); cp_commit();

    // Q fragments in registers for the entire kernel
    cp_wait<2>();
    __syncthreads();
    uint32_t qf[4][4];
    #pragma unroll
    for (int kc = 0; kc < 4; kc++)
        LDSM4(qf[kc], sb + (uint32_t)((wid*16 + (lane & 15)) * 144
                                      + kc*32 + (lane >> 4) * 16));

    float oacc[8][4];
    #pragma unroll
    for (int ni = 0; ni < 8; ni++)
        #pragma unroll
        for (int c = 0; c < 4; c++) oacc[ni][c] = 0.f;
    float m0 = -1e30f, m1 = -1e30f, l0 = 0.f, l1 = 0.f;

    const int rowA = qt*128 + wid*16 + (lane >> 2);   // row of c0/c1; +8 for c2/c3

    for (int kt = 0; kt < nkv; kt++) {
        cp_wait<1>();
        __syncthreads();
        const uint32_t Ks = sb + FQ_BYTES + (uint32_t)(kt & 1) * FKV_STAGE;
        const uint32_t Vs = Ks + 9216u;

        // S = Q K^T
        float sacc[8][4];
        #pragma unroll
        for (int ni = 0; ni < 8; ni++)
            #pragma unroll
            for (int c = 0; c < 4; c++) sacc[ni][c] = 0.f;
        #pragma unroll
        for (int kc = 0; kc < 4; kc++) {
            #pragma unroll
            for (int ni = 0; ni < 8; ni++) {
                uint32_t bb[2];
                LDSM2(bb, Ks + (uint32_t)((ni*8 + (lane & 7)) * 144
                                          + kc*32 + ((lane >> 3) & 1) * 16));
                MMA_F16(sacc[ni], qf[kc], bb);
            }
        }

        // scale + causal mask
        const bool needMask = (kt >= 2*qt);
        #pragma unroll
        for (int ni = 0; ni < 8; ni++) {
            const int cb = kt*64 + ni*8 + (lane & 3) * 2;
            #pragma unroll
            for (int c = 0; c < 4; c++) {
                float s = sacc[ni][c] * (1.0f / 64.0f);
                if (needMask) {
                    const int row = rowA + ((c >> 1) << 3);
                    const int col = cb + (c & 1);
                    if (col > row) s = -1e30f;
                }
                sacc[ni][c] = s;
            }
        }

        // online softmax (rows rowA and rowA+8); quad-wide reductions
        float mx0 = -1e30f, mx1 = -1e30f;
        #pragma unroll
        for (int ni = 0; ni < 8; ni++) {
            mx0 = fmaxf(mx0, fmaxf(sacc[ni][0], sacc[ni][1]));
            mx1 = fmaxf(mx1, fmaxf(sacc[ni][2], sacc[ni][3]));
        }
        mx0 = fmaxf(mx0, __shfl_xor_sync(0xffffffffu, mx0, 1));
        mx0 = fmaxf(mx0, __shfl_xor_sync(0xffffffffu, mx0, 2));
        mx1 = fmaxf(mx1, __shfl_xor_sync(0xffffffffu, mx1, 1));
        mx1 = fmaxf(mx1, __shfl_xor_sync(0xffffffffu, mx1, 2));
        const float mn0 = fmaxf(m0, mx0), mn1 = fmaxf(m1, mx1);
        const float al0 = __expf(m0 - mn0), al1 = __expf(m1 - mn1);
        m0 = mn0; m1 = mn1;

        float rs0 = 0.f, rs1 = 0.f;
        #pragma unroll
        for (int ni = 0; ni < 8; ni++) {
            sacc[ni][0] = __expf(sacc[ni][0] - mn0);
            sacc[ni][1] = __expf(sacc[ni][1] - mn0);
            sacc[ni][2] = __expf(sacc[ni][2] - mn1);
            sacc[ni][3] = __expf(sacc[ni][3] - mn1);
            rs0 += sacc[ni][0] + sacc[ni][1];
            rs1 += sacc[ni][2] + sacc[ni][3];
        }
        rs0 += __shfl_xor_sync(0xffffffffu, rs0, 1);
        rs0 += __shfl_xor_sync(0xffffffffu, rs0, 2);
        rs1 += __shfl_xor_sync(0xffffffffu, rs1, 1);
        rs1 += __shfl_xor_sync(0xffffffffu, rs1, 2);
        l0 = l0 * al0 + rs0;
        l1 = l1 * al1 + rs1;
        #pragma unroll
        for (int ni = 0; ni < 8; ni++) {
            oacc[ni][0] *= al0; oacc[ni][1] *= al0;
            oacc[ni][2] *= al1; oacc[ni][3] *= al1;
        }

        // pack P (C-frag -> A-frag layout)
        uint32_t pf[4][4];
        #pragma unroll
        for (int kc = 0; kc < 4; kc++) {
            pf[kc][0] = pack_h2(sacc[2*kc][0],   sacc[2*kc][1]);
            pf[kc][1] = pack_h2(sacc[2*kc][2],   sacc[2*kc][3]);
            pf[kc][2] = pack_h2(sacc[2*kc+1][0], sacc[2*kc+1][1]);
            pf[kc][3] = pack_h2(sacc[2*kc+1][2], sacc[2*kc+1][3]);
        }

        // O += P V   (V via ldmatrix.trans)
        #pragma unroll
        for (int kc = 0; kc < 4; kc++) {
            #pragma unroll
            for (int ni = 0; ni < 8; ni++) {
                uint32_t bv[2];
                LDSM2T(bv, Vs + (uint32_t)((kc*16 + (lane & 15)) * 144 + ni * 16));
                MMA_F16(oacc[ni], pf[kc], bv);
            }
        }

        __syncthreads();
        if (kt + 2 < nkv) loadKV(kt + 2, kt & 1);
        cp_commit();
    }

    // normalize + write O (b, s, h*64+dk) fp16
    const float inv0 = 1.0f / l0, inv1 = 1.0f / l1;
    #pragma unroll
    for (int half = 0; half < 2; half++) {
        const int rg = qt*128 + wid*16 + (lane >> 2) + half*8;
        const float inv = half ? inv1 : inv0;
        #pragma unroll
        for (int ni = 0; ni < 8; ni++) {
            const int dk = ni*8 + (lane & 3) * 2;
            *(__half2*)&O[((size_t)bidx * SS + rg) * DD + h*64 + dk] =
                __floats2half2_rn(oacc[ni][half*2] * inv, oacc[ni][half*2 + 1] * inv);
        }
    }
}

// ---------------------------------------------------------------------------
// Launch
// ---------------------------------------------------------------------------
extern "C" void kernel_launch(void* const* d_in, const int* in_sizes, int n_in,
                              void* d_out, int out_size)
{
    (void)in_sizes; (void)n_in; (void)out_size;
    const float* x      = (const float*)d_in[0];
    const float* wq     = (const float*)d_in[2];
    const float* wk     = (const float*)d_in[3];
    const float* wv     = (const float*)d_in[4];
    const float* wo     = (const float*)d_in[5];
    const float* w_up   = (const float*)d_in[6];
    const float* w_down = (const float*)d_in[7];
    float* out = (float*)d_out;

    float *x1;
    __half *qh, *kh, *vh, *oh, *x1h, *hh, *xh, *wqkvh, *woh, *wuph, *wdnh;
    cudaGetSymbolAddress((void**)&qh,  g_qh);
    cudaGetSymbolAddress((void**)&kh,  g_kh);
    cudaGetSymbolAddress((void**)&vh,  g_vh);
    cudaGetSymbolAddress((void**)&oh,  g_oh);
    cudaGetSymbolAddress((void**)&x1,  g_x1);
    cudaGetSymbolAddress((void**)&x1h, g_x1h);
    cudaGetSymbolAddress((void**)&hh,  g_hh);
    cudaGetSymbolAddress((void**)&xh,  g_xh);
    cudaGetSymbolAddress((void**)&wqkvh, g_wqkvh);
    cudaGetSymbolAddress((void**)&woh,   g_woh);
    cudaGetSymbolAddress((void**)&wuph,  g_wuph);
    cudaGetSymbolAddress((void**)&wdnh,  g_wdnh);

    cudaFuncSetAttribute(flash_hmma,   cudaFuncAttributeMaxDynamicSharedMemorySize, FSMEM);
    cudaFuncSetAttribute(gemm_hmma<0>, cudaFuncAttributeMaxDynamicSharedMemorySize, GSMEM);
    cudaFuncSetAttribute(gemm_hmma<1>, cudaFuncAttributeMaxDynamicSharedMemorySize, GSMEM);
    cudaFuncSetAttribute(gemm_hmma<2>, cudaFuncAttributeMaxDynamicSharedMemorySize, GSMEM);
    cudaFuncSetAttribute(gemm_hmma<3>, cudaFuncAttributeMaxDynamicSharedMemorySize, GSMEM);

    dim3 blk(256);

    // converts to fp16
    tohalf_kernel<<<MTOT*DD/4/256, blk>>>(x, xh, MTOT*DD);
    tohalf_kernel<<<DD*DD/4/256, blk>>>(wq, wqkvh,                    DD*DD);
    tohalf_kernel<<<DD*DD/4/256, blk>>>(wk, wqkvh + (size_t)DD*DD,    DD*DD);
    tohalf_kernel<<<DD*DD/4/256, blk>>>(wv, wqkvh + (size_t)2*DD*DD,  DD*DD);
    tohalf_kernel<<<DD*DD/4/256, blk>>>(wo, woh,                      DD*DD);
    tohalf_kernel<<<DFFF*DD/4/256, blk>>>(w_up, wuph,                 DFFF*DD);
    tohalf_kernel<<<DD*DFFF/4/256, blk>>>(w_down, wdnh,               DD*DFFF);

    // fused QKV projection (N=1536) -> fp16 q,k,v (b,h,s,dk)
    gemm_hmma<0><<<dim3(12, 64), blk, GSMEM>>>(xh, wqkvh, DD, nullptr, nullptr, qh, kh, vh);

    // causal flash attention (fp16 HMMA) -> oh fp16 (b,s,d)
    flash_hmma<<<dim3(SS/128, BB*HH), blk, FSMEM>>>(qh, kh, vh, oh);

    // x1 = 5/6 x + 1/18 (O wo^T)  (fp32 + fp16 copies)
    gemm_hmma<1><<<dim3(4, 64), blk, GSMEM>>>(oh, woh, DD, x1, x, x1h, nullptr, nullptr);

    // h = gelu(x1 w_up^T)/1.1289 -> fp16
    gemm_hmma<2><<<dim3(16, 64), blk, GSMEM>>>(x1h, wuph, DD, nullptr, nullptr, hh, nullptr, nullptr);

    // out = 5/6 x1 + 1/6 (h w_down^T)
    gemm_hmma<3><<<dim3(4, 64), blk, GSMEM>>>(hh, wdnh, DFFF, out, x1, nullptr, nullptr, nullptr);
}

// round 5
// speedup vs baseline: 6.9619x; 1.1022x over previous
#include <cuda_runtime.h>
#include <cuda_fp16.h>
#include <math.h>
#include <stdint.h>

// Problem constants
#define BB    2
#define SS    4096
#define DD    512
#define HH    8
#define DKK   64
#define DFFF  2048
#define MTOT  (BB*SS)          // 8192 rows

// softmax scale folded into Q: (1/64) * log2(e)
#define QSCALE (1.4426950408889634f / 64.0f)

// ---------------------------------------------------------------------------
// Scratch (static device buffers; allocation-free per harness rules)
// ---------------------------------------------------------------------------
__device__ __half g_qh[(size_t)BB*HH*SS*DKK];   // (b,h,s,dk) fp16 (pre-scaled)
__device__ __half g_kh[(size_t)BB*HH*SS*DKK];
__device__ __half g_vh[(size_t)BB*HH*SS*DKK];
__device__ __half g_oh[(size_t)MTOT*DD];        // attn out (b,s,d) fp16
__device__ float  g_x1[(size_t)MTOT*DD];        // post-attn residual fp32
__device__ __half g_x1h[(size_t)MTOT*DD];       // x1 fp16
__device__ __half g_hh [(size_t)MTOT*DFFF];     // gelu hidden fp16
__device__ __half g_xh [(size_t)MTOT*DD];       // x fp16
__device__ __half g_wqkvh[(size_t)3*DD*DD];     // [1536,512]
__device__ __half g_woh  [(size_t)DD*DD];       // [512,512]
__device__ __half g_wuph [(size_t)DFFF*DD];     // [2048,512]
__device__ __half g_wdnh [(size_t)DD*DFFF];     // [512,2048]

// ---------------------------------------------------------------------------
// PTX helpers (plain sm_100-compatible: cp.async + ldmatrix + mma.sync)
// ---------------------------------------------------------------------------
__device__ __forceinline__ uint32_t smem_u32(const void* p) {
    uint32_t a;
    asm("{ .reg .u64 t; cvta.to.shared.u64 t, %1; cvt.u32.u64 %0, t; }" : "=r"(a) : "l"(p));
    return a;
}
__device__ __forceinline__ void cp_async16(uint32_t dst, const void* src) {
    asm volatile("cp.async.cg.shared.global [%0], [%1], 16;" :: "r"(dst), "l"(src));
}
__device__ __forceinline__ void cp_commit() {
    asm volatile("cp.async.commit_group;" ::: "memory");
}
template<int N> __device__ __forceinline__ void cp_wait() {
    asm volatile("cp.async.wait_group %0;" :: "n"(N) : "memory");
}
__device__ __forceinline__ float ex2(float x) {
    float y;
    asm("ex2.approx.ftz.f32 %0, %1;" : "=f"(y) : "f"(x));
    return y;
}

#define LDSM4(r, addr) \
    asm volatile("ldmatrix.sync.aligned.m8n8.x4.shared.b16 {%0,%1,%2,%3}, [%4];" \
        : "=r"((r)[0]), "=r"((r)[1]), "=r"((r)[2]), "=r"((r)[3]) : "r"(addr))
#define LDSM4T(r, addr) \
    asm volatile("ldmatrix.sync.aligned.m8n8.x4.trans.shared.b16 {%0,%1,%2,%3}, [%4];" \
        : "=r"((r)[0]), "=r"((r)1 [0]), "=r"((r)[2]), "=r"((r)[3]) : "r"(addr))
#undef LDSM4T
#define LDSM4T(r, addr) \
    asm volatile("ldmatrix.sync.aligned.m8n8.x4.trans.shared.b16 {%0,%1,%2,%3}, [%4];" \
        : "=r"((r)[0]), "=r"((r)[1]), "=r"((r)[2]), "=r"((r)[3]) : "r"(addr))
#define MMA_F16(d, a, b) \
    asm volatile("mma.sync.aligned.m16n8k16.row.col.f32.f16.f16.f32 " \
        "{%0,%1,%2,%3}, {%4,%5,%6,%7}, {%8,%9}, {%0,%1,%2,%3};" \
        : "+f"((d)[0]), "+f"((d)[1]), "+f"((d)[2]), "+f"((d)[3]) \
        : "r"((a)[0]), "r"((a)[1]), "r"((a)[2]), "r"((a)[3]), "r"((b)[0]), "r"((b)[1]))

__device__ __forceinline__ uint32_t pack_h2(float a, float b) {
    __half2 t = __floats2half2_rn(a, b);
    return *reinterpret_cast<uint32_t*>(&t);
}

// ---------------------------------------------------------------------------
// Fused fp32 -> fp16 convert of x + all weights, one launch.
// Linear index in float4 units; segment lookup by cumulative offsets.
// ---------------------------------------------------------------------------
#define CU_X   1048576                       // MTOT*DD/4
#define CU_W   65536                         // DD*DD/4
#define CU_UP  262144                        // DFFF*DD/4
#define CVT_TOTAL (CU_X + 4*CU_W + 2*CU_UP)  // 1835008 units
#define CVT_BLOCKS (CVT_TOTAL / 256)         // 7168

__global__ __launch_bounds__(256)
void convert_all(const float* __restrict__ x,  const float* __restrict__ wq,
                 const float* __restrict__ wk, const float* __restrict__ wv,
                 const float* __restrict__ wo, const float* __restrict__ wup,
                 const float* __restrict__ wdn,
                 __half* __restrict__ xh, __half* __restrict__ wqkvh,
                 __half* __restrict__ woh, __half* __restrict__ wuph,
                 __half* __restrict__ wdnh)
{
    int u = blockIdx.x * 256 + threadIdx.x;
    const float* src; __half* dst; int off;
    if (u < CU_X)                       { src = x;   dst = xh;    off = u; }
    else if (u < CU_X + CU_W)           { src = wq;  dst = wqkvh; off = u - CU_X; }
    else if (u < CU_X + 2*CU_W)         { src = wk;  dst = wqkvh + (size_t)DD*DD;   off = u - CU_X - CU_W; }
    else if (u < CU_X + 3*CU_W)         { src = wv;  dst = wqkvh + (size_t)2*DD*DD; off = u - CU_X - 2*CU_W; }
    else if (u < CU_X + 4*CU_W)         { src = wo;  dst = woh;   off = u - CU_X - 3*CU_W; }
    else if (u < CU_X + 4*CU_W + CU_UP) { src = wup; dst = wuph;  off = u - CU_X - 4*CU_W; }
    else                                { src = wdn; dst = wdnh;  off = u - CU_X - 4*CU_W - CU_UP; }
    float4 v = *(const float4*)(src + (size_t)off * 4);
    __half2 a = __floats2half2_rn(v.x, v.y);
    __half2 b = __floats2half2_rn(v.z, v.w);
    *reinterpret_cast<uint2*>(dst + (size_t)off * 4) =
        make_uint2(*(uint32_t*)&a, *(uint32_t*)&b);
}

// ---------------------------------------------------------------------------
// HMMA GEMM: C[m,n] = sum_k A[m,k] * W[n,k]  (fp16 in, fp32 accum), M=8192.
// 128x128 tile, BK=64, 8 warps (2m x 4n), 3-stage cp.async, 1 sync/iter.
// EPI: 0 = write fp16 q/k/v scatter to (b,h,s,dk) (N=1536), q pre-scaled
//      1 = x1 = 5/6 res + acc/18 -> fp32 fo and fp16 h0
//      2 = gelu(acc)/1.1289 -> fp16 h0 (C=2048)
//      3 = out = 5/6 res + acc/6 -> fp32 fo
// ---------------------------------------------------------------------------
#define GSTAGE 36864
#define GSMEM  (3 * GSTAGE)   // 110592

template<int EPI>
__global__ __launch_bounds__(256)
void gemm_hmma(const __half* __restrict__ A, const __half* __restrict__ W,
               int Kp, float* __restrict__ fo, const float* __restrict__ res,
               __half* __restrict__ h0, __half* __restrict__ h1,
               __half* __restrict__ h2)
{
    extern __shared__ char smem[];
    const uint32_t sb = smem_u32(smem);
    const int tid = threadIdx.x, wid = tid >> 5, lane = tid & 31;
    const int bn = blockIdx.x, bm = blockIdx.y;
    const int wm = wid & 1, wn = wid >> 1;

    float acc[4][4][4];
    #pragma unroll
    for (int mi = 0; mi < 4; mi++)
        #pragma unroll
        for (int ni = 0; ni < 4; ni++)
            #pragma unroll
            for (int c = 0; c < 4; c++) acc[mi][ni][c] = 0.f;

    auto load_chunk = [&](int c, int st) {
        const uint32_t base = sb + (uint32_t)st * GSTAGE;
        #pragma unroll
        for (int u = 0; u < 8; u++) {
            int seg = tid + u * 256;         // 0..2047
            int isB = seg >> 10;
            int r   = (seg >> 3) & 127;
            int sc  = seg & 7;
            const __half* src = isB ? W : A;
            int rowg = (isB ? bn : bm) * 128 + r;
            const char* g = (const char*)(src + (size_t)rowg * Kp + c * 64) + sc * 16;
            uint32_t d = base + (isB ? 18432u : 0u) + (uint32_t)(r * 144 + sc * 16);
            cp_async16(d, g);
        }
    };

    load_chunk(0, 0); cp_commit();
    load_chunk(1, 1); cp_commit();

    const int nch = Kp >> 6;
    for (int i = 0; i < nch; i++) {
        cp_wait<1>();
        __syncthreads();
        if (i + 2 < nch) load_chunk(i + 2, (i + 2) % 3);
        cp_commit();
        {
            const uint32_t As = sb + (uint32_t)(i % 3) * GSTAGE;
            const uint32_t Bs = As + 18432u;
            #pragma unroll
            for (int ks = 0; ks < 4; ks++) {
                uint32_t a[4][4], b[2][4];
                #pragma unroll
                for (int mi = 0; mi < 4; mi++)
                    LDSM4(a[mi], As + (uint32_t)((wm*64 + mi*16 + (lane & 15)) * 144
                                                 + ks*32 + (lane >> 4) * 16));
                #pragma unroll
                for (int p = 0; p < 2; p++)
                    LDSM4(b[p], Bs + (uint32_t)((wn*32 + p*16 + ((lane & 16) >> 1)
                                                 + (lane & 7)) * 144
                                                + ks*32 + ((lane >> 3) & 1) * 16));
                #pragma unroll
                for (int mi = 0; mi < 4; mi++)
                    #pragma unroll
                    for (int ni = 0; ni < 4; ni++)
                        MMA_F16(acc[mi][ni], a[mi], b[ni >> 1] + (ni & 1) * 2);
            }
        }
    }

    // epilogue straight from registers
    #pragma unroll
    for (int mi = 0; mi < 4; mi++) {
        #pragma unroll
        for (int half = 0; half < 2; half++) {
            const int rg = bm*128 + wm*64 + mi*16 + (lane >> 2) + half*8;
            #pragma unroll
            for (int ni = 0; ni < 4; ni++) {
                const int cg = bn*128 + wn*32 + ni*8 + (lane & 3) * 2;
                float v0 = acc[mi][ni][half*2 + 0];
                float v1 = acc[mi][ni][half*2 + 1];
                if (EPI == 0) {
                    const int which = cg >> 9, h = (cg >> 6) & 7, dk = cg & 63;
                    const int bb = rg >> 12, s = rg & (SS - 1);
                    if (which == 0) { v0 *= QSCALE; v1 *= QSCALE; }
                    __half* dst = (which == 0) ? h0 : ((which == 1) ? h1 : h2);
                    *(__half2*)&dst[((size_t)(bb*HH + h) * SS + s) * 64 + dk] =
                        __floats2half2_rn(v0, v1);
                } else if (EPI == 1) {
                    const float2 xr = *(const float2*)&res[(size_t)rg * DD + cg];
                    float u0 = (5.0f/6.0f) * xr.x + v0 * (1.0f/18.0f);
                    float u1 = (5.0f/6.0f) * xr.y + v1 * (1.0f/18.0f);
                    *(float2*)&fo[(size_t)rg * DD + cg] = make_float2(u0, u1);
                    *(__half2*)&h0[(size_t)rg * DD + cg] = __floats2half2_rn(u0, u1);
                } else if (EPI == 2) {
                    float g0 = 0.5f * v0 * (1.0f + erff(v0 * 0.70710678118654752f)) * (1.0f/1.1289f);
                    float g1 = 0.5f * v1 * (1.0f + erff(v1 * 0.70710678118654752f)) * (1.0f/1.1289f);
                    *(__half2*)&h0[(size_t)rg * DFFF + cg] = __floats2half2_rn(g0, g1);
                } else {
                    const float2 xr = *(const float2*)&res[(size_t)rg * DD + cg];
                    *(float2*)&fo[(size_t)rg * DD + cg] =
                        make_float2((5.0f/6.0f) * xr.x + v0 * (1.0f/6.0f),
                                    (5.0f/6.0f) * xr.y + v1 * (1.0f/6.0f));
                }
            }
        }
    }
}

// ---------------------------------------------------------------------------
// HMMA causal flash attention. CTA = 128 q-rows, 8 warps (one m16 each),
// KV tile 64, DK=64, fp16 ops, fp32 softmax/accum (log2 domain).
// 3-stage KV ring, 1 sync/iter, target occupancy 2.
// ---------------------------------------------------------------------------
#define FQ_BYTES   18432              // 128 x 72 halves
#define FKV_STAGE  18432              // (64 + 64) x 72 halves
#define FSMEM      (FQ_BYTES + 3 * FKV_STAGE)   // 73728

__global__ __launch_bounds__(256, 2)
void flash_hmma(const __half* __restrict__ Q, const __half* __restrict__ K,
                const __half* __restrict__ V, __half* __restrict__ O)
{
    extern __shared__ char smem[];
    const uint32_t sb = smem_u32(smem);
    const int tid = threadIdx.x, wid = tid >> 5, lane = tid & 31;

    const int bh = blockIdx.y;
    const int qt = gridDim.x - 1 - blockIdx.x;    // heavy tiles first
    const int bidx = bh >> 3, h = bh & 7;

    const __half* Qb = Q + (size_t)bh * SS * DKK;
    const __half* Kb = K + (size_t)bh * SS * DKK;
    const __half* Vb = V + (size_t)bh * SS * DKK;

    // ---- load Q tile (128 x 64) ----
    {
        #pragma unroll
        for (int u = 0; u < 4; u++) {
            int seg = tid + u * 256;           // 0..1023
            int r   = seg >> 3;
            int sc  = seg & 7;
            const char* g = (const char*)(Qb + ((size_t)(qt*128 + r)) * 64) + sc * 16;
            cp_async16(sb + (uint32_t)(r * 144 + sc * 16), g);
        }
        cp_commit();
    }

    auto loadKV = [&](int t, int st) {
        const uint32_t base = sb + FQ_BYTES + (uint32_t)st * FKV_STAGE;
        #pragma unroll
        for (int u = 0; u < 4; u++) {
            int seg = tid + u * 256;           // 0..1023
            int isV = seg >> 9;
            int r   = (seg >> 3) & 63;
            int sc  = seg & 7;
            const __half* src = isV ? Vb : Kb;
            const char* g = (const char*)(src + ((size_t)(t*64 + r)) * 64) + sc * 16;
            cp_async16(base + (isV ? 9216u : 0u) + (uint32_t)(r * 144 + sc * 16), g);
        }
    };

    const int nkv = 2 * qt + 2;
    loadKV(0, 0); cp_commit();
    loadKV(1, 1); cp_commit();

    // Q fragments in registers for the entire kernel
    cp_wait<2>();
    __syncthreads();
    uint32_t qf[4][4];
    #pragma unroll
    for (int kc = 0; kc < 4; kc++)
        LDSM4(qf[kc], sb + (uint32_t)((wid*16 + (lane & 15)) * 144
                                      + kc*32 + (lane >> 4) * 16));

    float oacc[8][4];
    #pragma unroll
    for (int ni = 0; ni < 8; ni++)
        #pragma unroll
        for (int c = 0; c < 4; c++) oacc[ni][c] = 0.f;
    float m0 = -1e30f, m1 = -1e30f, l0 = 0.f, l1 = 0.f;

    const int rowA = qt*128 + wid*16 + (lane >> 2);   // row of c0/c1; +8 for c2/c3

    for (int kt = 0; kt < nkv; kt++) {
        cp_wait<1>();
        __syncthreads();
        if (kt + 2 < nkv) loadKV(kt + 2, (kt + 2) % 3);
        cp_commit();

        const uint32_t Ks = sb + FQ_BYTES + (uint32_t)(kt % 3) * FKV_STAGE;
        const uint32_t Vs = Ks + 9216u;

        // S = Q K^T  (Q pre-scaled by log2e/64 -> scores already in log2 domain)
        float sacc[8][4];
        #pragma unroll
        for (int ni = 0; ni < 8; ni++)
            #pragma unroll
            for (int c = 0; c < 4; c++) sacc[ni][c] = 0.f;
        #pragma unroll
        for (int kc = 0; kc < 4; kc++) {
            #pragma unroll
            for (int p = 0; p < 4; p++) {
                uint32_t kb[4];
                LDSM4(kb, Ks + (uint32_t)((p*16 + ((lane & 16) >> 1) + (lane & 7)) * 144
                                          + kc*32 + ((lane >> 3) & 1) * 16));
                MMA_F16(sacc[2*p],     qf[kc], kb);
                MMA_F16(sacc[2*p + 1], qf[kc], kb + 2);
            }
        }

        // causal mask (only on the last two tiles)
        if (kt >= 2*qt) {
            #pragma unroll
            for (int ni = 0; ni < 8; ni++) {
                const int cb = kt*64 + ni*8 + (lane & 3) * 2;
                #pragma unroll
                for (int c = 0; c < 4; c++) {
                    const int row = rowA + ((c >> 1) << 3);
                    const int col = cb + (c & 1);
                    if (col > row) sacc[ni][c] = -1e30f;
                }
            }
        }

        // online softmax in log2 domain (rows rowA and rowA+8)
        float mx0 = -1e30f, mx1 = -1e30f;
        #pragma unroll
        for (int ni = 0; ni < 8; ni++) {
            mx0 = fmaxf(mx0, fmaxf(sacc[ni][0], sacc[ni][1]));
            mx1 = fmaxf(mx1, fmaxf(sacc[ni][2], sacc[ni][3]));
        }
        mx0 = fmaxf(mx0, __shfl_xor_sync(0xffffffffu, mx0, 1));
        mx0 = fmaxf(mx0, __shfl_xor_sync(0xffffffffu, mx0, 2));
        mx1 = fmaxf(mx1, __shfl_xor_sync(0xffffffffu, mx1, 1));
        mx1 = fmaxf(mx1, __shfl_xor_sync(0xffffffffu, mx1, 2));
        const float mn0 = fmaxf(m0, mx0), mn1 = fmaxf(m1, mx1);
        const float al0 = ex2(m0 - mn0), al1 = ex2(m1 - mn1);
        m0 = mn0; m1 = mn1;

        float rs0 = 0.f, rs1 = 0.f;
        #pragma unroll
        for (int ni = 0; ni < 8; ni++) {
            sacc[ni][0] = ex2(sacc[ni][0] - mn0);
            sacc[ni][1] = ex2(sacc[ni][1] - mn0);
            sacc[ni][2] = ex2(sacc[ni][2] - mn1);
            sacc[ni][3] = ex2(sacc[ni][3] - mn1);
            rs0 += sacc[ni][0] + sacc[ni][1];
            rs1 += sacc[ni][2] + sacc[ni][3];
        }
        rs0 += __shfl_xor_sync(0xffffffffu, rs0, 1);
        rs0 += __shfl_xor_sync(0xffffffffu, rs0, 2);
        rs1 += __shfl_xor_sync(0xffffffffu, rs1, 1);
        rs1 += __shfl_xor_sync(0xffffffffu, rs1, 2);
        l0 = l0 * al0 + rs0;
        l1 = l1 * al1 + rs1;
        #pragma unroll
        for (int ni = 0; ni < 8; ni++) {
            oacc[ni][0] *= al0; oacc[ni][1] *= al0;
            oacc[ni][2] *= al1; oacc[ni][3] *= al1;
        }

        // pack P (C-frag -> A-frag layout)
        uint32_t pf[4][4];
        #pragma unroll
        for (int kc = 0; kc < 4; kc++) {
            pf[kc][0] = pack_h2(sacc[2*kc][0],   sacc[2*kc][1]);
            pf[kc][1] = pack_h2(sacc[2*kc][2],   sacc[2*kc][3]);
            pf[kc][2] = pack_h2(sacc[2*kc+1][0], sacc[2*kc+1][1]);
            pf[kc][3] = pack_h2(sacc[2*kc+1][2], sacc[2*kc+1][3]);
        }

        // O += P V   (V via ldmatrix.x4.trans: two n8 tiles per load)
        #pragma unroll
        for (int kc = 0; kc < 4; kc++) {
            #pragma unroll
            for (int p = 0; p < 4; p++) {
                uint32_t vv[4];
                LDSM4T(vv, Vs + (uint32_t)((kc*16 + (lane & 15)) * 144
                                           + (2*p + (lane >> 4)) * 16));
                MMA_F16(oacc[2*p],     pf[kc], vv);
                MMA_F16(oacc[2*p + 1], pf[kc], vv + 2);
            }
        }
    }

    // normalize + write O (b, s, h*64+dk) fp16
    const float inv0 = 1.0f / l0, inv1 = 1.0f / l1;
    #pragma unroll
    for (int half = 0; half < 2; half++) {
        const int rg = qt*128 + wid*16 + (lane >> 2) + half*8;
        const float inv = half ? inv1 : inv0;
        #pragma unroll
        for (int ni = 0; ni < 8; ni++) {
            const int dk = ni*8 + (lane & 3) * 2;
            *(__half2*)&O[((size_t)bidx * SS + rg) * DD + h*64 + dk] =
                __floats2half2_rn(oacc[ni][half*2] * inv, oacc[ni][half*2 + 1] * inv);
        }
    }
}

// ---------------------------------------------------------------------------
// Launch
// ---------------------------------------------------------------------------
extern "C" void kernel_launch(void* const* d_in, const int* in_sizes, int n_in,
                              void* d_out, int out_size)
{
    (void)in_sizes; (void)n_in; (void)out_size;
    const float* x      = (const float*)d_in[0];
    const float* wq     = (const float*)d_in[2];
    const float* wk     = (const float*)d_in[3];
    const float* wv     = (const float*)d_in[4];
    const float* wo     = (const float*)d_in[5];
    const float* w_up   = (const float*)d_in[6];
    const float* w_down = (const float*)d_in[7];
    float* out = (float*)d_out;

    float *x1;
    __half *qh, *kh, *vh, *oh, *x1h, *hh, *xh, *wqkvh, *woh, *wuph, *wdnh;
    cudaGetSymbolAddress((void**)&qh,  g_qh);
    cudaGetSymbolAddress((void**)&kh,  g_kh);
    cudaGetSymbolAddress((void**)&vh,  g_vh);
    cudaGetSymbolAddress((void**)&oh,  g_oh);
    cudaGetSymbolAddress((void**)&x1,  g_x1);
    cudaGetSymbolAddress((void**)&x1h, g_x1h);
    cudaGetSymbolAddress((void**)&hh,  g_hh);
    cudaGetSymbolAddress((void**)&xh,  g_xh);
    cudaGetSymbolAddress((void**)&wqkvh, g_wqkvh);
    cudaGetSymbolAddress((void**)&woh,   g_woh);
    cudaGetSymbolAddress((void**)&wuph,  g_wuph);
    cudaGetSymbolAddress((void**)&wdnh,  g_wdnh);

    cudaFuncSetAttribute(flash_hmma,   cudaFuncAttributeMaxDynamicSharedMemorySize, FSMEM);
    cudaFuncSetAttribute(gemm_hmma<0>, cudaFuncAttributeMaxDynamicSharedMemorySize, GSMEM);
    cudaFuncSetAttribute(gemm_hmma<1>, cudaFuncAttributeMaxDynamicSharedMemorySize, GSMEM);
    cudaFuncSetAttribute(gemm_hmma<2>, cudaFuncAttributeMaxDynamicSharedMemorySize, GSMEM);
    cudaFuncSetAttribute(gemm_hmma<3>, cudaFuncAttributeMaxDynamicSharedMemorySize, GSMEM);

    dim3 blk(256);

    // one fused convert launch (x + all weights)
    convert_all<<<CVT_BLOCKS, blk>>>(x, wq, wk, wv, wo, w_up, w_down,
                                     xh, wqkvh, woh, wuph, wdnh);

    // fused QKV projection (N=1536) -> fp16 q,k,v (b,h,s,dk); q pre-scaled
    gemm_hmma<0><<<dim3(12, 64), blk, GSMEM>>>(xh, wqkvh, DD, nullptr, nullptr, qh, kh, vh);

    // causal flash attention (fp16 HMMA, log2-domain softmax) -> oh fp16
    flash_hmma<<<dim3(SS/128, BB*HH), blk, FSMEM>>>(qh, kh, vh, oh);

    // x1 = 5/6 x + 1/18 (O wo^T)  (fp32 + fp16 copies)
    gemm_hmma<1><<<dim3(4, 64), blk, GSMEM>>>(oh, woh, DD, x1, x, x1h, nullptr, nullptr);

    // h = gelu(x1 w_up^T)/1.1289 -> fp16
    gemm_hmma<2><<<dim3(16, 64), blk, GSMEM>>>(x1h, wuph, DD, nullptr, nullptr, hh, nullptr, nullptr);

    // out = 5/6 x1 + 1/6 (h w_down^T)
    gemm_hmma<3><<<dim3(4, 64), blk, GSMEM>>>(hh, wdnh, DFFF, out, x1, nullptr, nullptr, nullptr);
}